// round 1
// baseline (speedup 1.0000x reference)
#include <cuda_runtime.h>
#include <cuda_bf16.h>

// GAT: N=100000 nodes, E=1600000 edges, F_IN=128, H=4 heads, C=32 ch/head.
// Pipeline:
//   1) k_gemm:   h = x@W  (+ fused a_src/a_dst epilogue reductions)
//   2) CSR build by dst: zero -> histogram -> 3-kernel scan -> scatter
//   3) k_agg:    one warp per dst node; single pass softmax-aggregate:
//                out = (sum_e p_e * h[src_e]) / (sum_e p_e + 1e-16), p=exp(lrelu(e))
//                (max-subtraction skipped: |e| bounded ~6, exp cannot overflow)

#define NN 100000
#define EE 1600000
#define FF 128
#define HH 4
#define HC 128
#define SLOPE 0.2f
#define SCAN_NB 98   // ceil(100000/1024)

// ---- scratch (device globals; no allocation allowed) ----
__device__ float g_h[(size_t)NN * HC];     // projected features [N,128]
__device__ float g_as[NN * HH];            // a_src [N,H]
__device__ float g_ad[NN * HH];            // a_dst [N,H]
__device__ int   g_cnt[NN];
__device__ int   g_off[NN + 1];
__device__ int   g_cur[NN];
__device__ int   g_csr[EE];
__device__ int   g_bsums[128];
__device__ int   g_is64;

// ------------------------------------------------------------------
// edge-index dtype detection (jax may deliver int32 despite int64 request)
__global__ void k_detect(const void* ei) {
    if (threadIdx.x == 0 && blockIdx.x == 0) {
        const int* w = (const int*)ei;
        int is64 = 1;
        #pragma unroll
        for (int i = 0; i < 16; i++) {
            if (w[2 * i + 1] != 0) is64 = 0;
        }
        g_is64 = is64;
    }
}

__device__ __forceinline__ int load_idx(const void* ei, long long pos) {
    if (g_is64) return (int)((const long long*)ei)[pos];
    return ((const int*)ei)[pos];
}

// ------------------------------------------------------------------
// GEMM: h = x @ W   (x:[N,128], W:[128,128]) + fused attention dots.
// Block = 256 threads (8 warps). Each warp computes 4 rows x 128 cols.
// x tile (32 rows) staged in smem; W streamed via __ldg (L1-resident, 64KB).
__global__ __launch_bounds__(256) void k_gemm(
    const float* __restrict__ x, const float* __restrict__ W,
    const float* __restrict__ attS, const float* __restrict__ attD)
{
    __shared__ float sx[32 * FF];           // 16 KB
    const int warp = threadIdx.x >> 5;
    const int lane = threadIdx.x & 31;
    const int row0 = blockIdx.x * 32;       // N divisible by 32 (3125 blocks)

    // stage x tile: 32 rows * 32 float4
    const float4* x4 = (const float4*)(x + (size_t)row0 * FF);
    float4* sx4 = (float4*)sx;
    #pragma unroll
    for (int i = threadIdx.x; i < 32 * 32; i += 256) sx4[i] = x4[i];
    __syncthreads();

    const int r0 = warp * 4;
    const float4* W4 = (const float4*)W;

    float4 a0 = {0,0,0,0}, a1 = {0,0,0,0}, a2 = {0,0,0,0}, a3 = {0,0,0,0};
    #pragma unroll 4
    for (int k = 0; k < FF; k++) {
        float4 w = __ldg(&W4[k * 32 + lane]);
        float x0 = sx[(r0 + 0) * FF + k];
        float x1 = sx[(r0 + 1) * FF + k];
        float x2 = sx[(r0 + 2) * FF + k];
        float x3 = sx[(r0 + 3) * FF + k];
        a0.x += w.x * x0; a0.y += w.y * x0; a0.z += w.z * x0; a0.w += w.w * x0;
        a1.x += w.x * x1; a1.y += w.y * x1; a1.z += w.z * x1; a1.w += w.w * x1;
        a2.x += w.x * x2; a2.y += w.y * x2; a2.z += w.z * x2; a2.w += w.w * x2;
        a3.x += w.x * x3; a3.y += w.y * x3; a3.z += w.z * x3; a3.w += w.w * x3;
    }

    // epilogue: store h rows + per-head attention dots
    float4 vS = __ldg(&((const float4*)attS)[lane]);  // att laid out [H*C]=128 matches cols
    float4 vD = __ldg(&((const float4*)attD)[lane]);
    float4* h4 = (float4*)g_h;
    const int hd = lane >> 3;

    float4 accs[4] = {a0, a1, a2, a3};
    #pragma unroll
    for (int r = 0; r < 4; r++) {
        int row = row0 + r0 + r;
        float4 a = accs[r];
        h4[(size_t)row * 32 + lane] = a;
        float s1 = a.x * vS.x + a.y * vS.y + a.z * vS.z + a.w * vS.w;
        float s2 = a.x * vD.x + a.y * vD.y + a.z * vD.z + a.w * vD.w;
        // reduce across the 8 lanes of each head (groups of 8 contiguous lanes)
        #pragma unroll
        for (int o = 4; o >= 1; o >>= 1) {
            s1 += __shfl_down_sync(0xFFFFFFFFu, s1, o);
            s2 += __shfl_down_sync(0xFFFFFFFFu, s2, o);
        }
        if ((lane & 7) == 0) {
            g_as[row * HH + hd] = s1;
            g_ad[row * HH + hd] = s2;
        }
    }
}

// ------------------------------------------------------------------
__global__ void k_zero() {
    int i = blockIdx.x * blockDim.x + threadIdx.x;
    if (i < NN) g_cnt[i] = 0;
}

__global__ void k_hist(const void* __restrict__ ei) {
    int e = blockIdx.x * blockDim.x + threadIdx.x;
    if (e < EE) {
        int d = load_idx(ei, (long long)EE + e);
        atomicAdd(&g_cnt[d], 1);
    }
}

// 3-kernel exclusive scan of g_cnt -> g_off (and g_cur copy)
__global__ void k_scan1() {
    __shared__ int s[1024];
    int tid = threadIdx.x;
    int i = blockIdx.x * 1024 + tid;
    int v = (i < NN) ? g_cnt[i] : 0;
    s[tid] = v;
    __syncthreads();
    for (int o = 1; o < 1024; o <<= 1) {
        int t = (tid >= o) ? s[tid - o] : 0;
        __syncthreads();
        s[tid] += t;
        __syncthreads();
    }
    if (i < NN) g_off[i] = s[tid] - v;   // exclusive, block-local
    if (tid == 1023) g_bsums[blockIdx.x] = s[1023];
}

__global__ void k_scan2() {
    __shared__ int s[128];
    int tid = threadIdx.x;
    int v = (tid < SCAN_NB) ? g_bsums[tid] : 0;
    s[tid] = v;
    __syncthreads();
    for (int o = 1; o < 128; o <<= 1) {
        int t = (tid >= o) ? s[tid - o] : 0;
        __syncthreads();
        s[tid] += t;
        __syncthreads();
    }
    g_bsums[tid] = s[tid] - v;           // exclusive
}

__global__ void k_scan3() {
    int i = blockIdx.x * 1024 + threadIdx.x;
    if (i < NN) {
        int o = g_off[i] + g_bsums[blockIdx.x];
        g_off[i] = o;
        g_cur[i] = o;
    }
    if (i == 0) g_off[NN] = EE;
}

__global__ void k_scatter(const void* __restrict__ ei) {
    int e = blockIdx.x * blockDim.x + threadIdx.x;
    if (e < EE) {
        int s = load_idx(ei, e);
        int d = load_idx(ei, (long long)EE + e);
        int pos = atomicAdd(&g_cur[d], 1);
        g_csr[pos] = s;
    }
}

// ------------------------------------------------------------------
// Aggregation: one warp per dst node. Lane owns 4 contiguous channels
// (head = lane/8). Single fused pass: p = exp(lrelu(a_src[s]+a_dst[i])),
// acc += p * h[s], psum += p; self-loop appended; out = acc/psum (+bias).
__global__ __launch_bounds__(256) void k_agg(
    const float* __restrict__ bias, float* __restrict__ out)
{
    const int warp = threadIdx.x >> 5;
    const int lane = threadIdx.x & 31;
    const int i = blockIdx.x * 8 + warp;
    if (i >= NN) return;

    const int hd = lane >> 3;
    const float adv = g_ad[i * HH + hd];
    const int beg = g_off[i];
    const int end = g_off[i + 1];
    const float4* __restrict__ h4 = (const float4*)g_h;

    float4 acc = {0.f, 0.f, 0.f, 0.f};
    float ps = 0.f;

    int e = beg;
    int sn = (e < end) ? __ldg(&g_csr[e]) : 0;
    while (e < end) {
        int s = sn;
        e++;
        if (e < end) sn = __ldg(&g_csr[e]);
        float ev = __ldg(&g_as[s * HH + hd]) + adv;
        ev = ev > 0.f ? ev : SLOPE * ev;
        float p = __expf(ev);
        float4 hv = h4[(size_t)s * 32 + lane];
        acc.x += p * hv.x; acc.y += p * hv.y;
        acc.z += p * hv.z; acc.w += p * hv.w;
        ps += p;
    }
    // self loop (src = dst = i)
    {
        float ev = __ldg(&g_as[i * HH + hd]) + adv;
        ev = ev > 0.f ? ev : SLOPE * ev;
        float p = __expf(ev);
        float4 hv = h4[(size_t)i * 32 + lane];
        acc.x += p * hv.x; acc.y += p * hv.y;
        acc.z += p * hv.z; acc.w += p * hv.w;
        ps += p;
    }

    const float inv = 1.0f / (ps + 1e-16f);
    float4 b = __ldg(&((const float4*)bias)[lane]);
    float4 o;
    o.x = acc.x * inv + b.x;
    o.y = acc.y * inv + b.y;
    o.z = acc.z * inv + b.z;
    o.w = acc.w * inv + b.w;
    ((float4*)out)[(size_t)i * 32 + lane] = o;
}

// ------------------------------------------------------------------
extern "C" void kernel_launch(void* const* d_in, const int* in_sizes, int n_in,
                              void* d_out, int out_size)
{
    const float* x    = (const float*)d_in[0];
    const float* W    = (const float*)d_in[1];
    const float* attS = (const float*)d_in[2];
    const float* attD = (const float*)d_in[3];
    const float* bias = (const float*)d_in[4];
    const void*  ei   = d_in[5];
    float* out = (float*)d_out;

    k_detect<<<1, 32>>>(ei);
    k_gemm<<<NN / 32, 256>>>(x, W, attS, attD);
    k_zero<<<(NN + 255) / 256, 256>>>();
    k_hist<<<(EE + 255) / 256, 256>>>(ei);
    k_scan1<<<SCAN_NB, 1024>>>();
    k_scan2<<<1, 128>>>();
    k_scan3<<<SCAN_NB, 1024>>>();
    k_scatter<<<(EE + 255) / 256, 256>>>(ei);
    k_agg<<<(NN + 7) / 8, 256>>>(bias, out);
}

// round 2
// speedup vs baseline: 1.1048x; 1.1048x over previous
#include <cuda_runtime.h>
#include <cuda_fp16.h>
#include <cuda_bf16.h>

// GAT N=100000, E=1600000, F=128 -> H*C=128.
// R2: tf32 mma.sync GEMM (fp32 SIMT FFMA is rt=2 => 36TF/s wall),
//     h stored fp16 (halves k_agg L2 gather traffic), att dots in small kernel,
//     k_agg 2-deep pipelined.

#define NN 100000
#define EE 1600000
#define FF 128
#define HH 4
#define SLOPE 0.2f
#define SCAN_NB 98

// smem strides (uints/floats) chosen for conflict-free mma fragment LDS
#define SXS 132   // x tile stride: bank = (4g + t4) % 32, all distinct
#define SWS 136   // W tile stride: bank = (8t4 + g) % 32, all distinct
#define SMEM_BYTES ((64 * SXS + 128 * SWS) * 4)   // 103424 B

// ---- device scratch ----
__device__ __half g_h16[(size_t)NN * FF];  // projected features, fp16 [N,128]
__device__ float  g_as[NN * HH];
__device__ float  g_ad[NN * HH];
__device__ int    g_cnt[NN];
__device__ int    g_off[NN + 1];
__device__ int    g_cur[NN];
__device__ int    g_csr[EE];
__device__ int    g_bsums[128];
__device__ int    g_is64;

// ------------------------------------------------------------------
__device__ __forceinline__ unsigned f2tf32(float f) {
    unsigned u;
    asm("cvt.rna.tf32.f32 %0, %1;" : "=r"(u) : "f"(f));
    return u;
}

__device__ __forceinline__ void mma_tf32(float c[4], unsigned a0, unsigned a1,
                                         unsigned a2, unsigned a3,
                                         unsigned b0, unsigned b1) {
    asm volatile(
        "mma.sync.aligned.m16n8k8.row.col.f32.tf32.tf32.f32 "
        "{%0,%1,%2,%3}, {%4,%5,%6,%7}, {%8,%9}, {%0,%1,%2,%3};"
        : "+f"(c[0]), "+f"(c[1]), "+f"(c[2]), "+f"(c[3])
        : "r"(a0), "r"(a1), "r"(a2), "r"(a3), "r"(b0), "r"(b1));
}

// ------------------------------------------------------------------
// init: zero histogram + (block 0) edge dtype detect
__global__ void k_init(const void* ei) {
    int i = blockIdx.x * blockDim.x + threadIdx.x;
    if (i < NN) g_cnt[i] = 0;
    if (i == 0) {
        const int* w = (const int*)ei;
        int is64 = 1;
        #pragma unroll
        for (int j = 0; j < 16; j++)
            if (w[2 * j + 1] != 0) is64 = 0;
        g_is64 = is64;
    }
}

__device__ __forceinline__ int load_idx(const void* ei, long long pos) {
    if (g_is64) return (int)((const long long*)ei)[pos];
    return ((const int*)ei)[pos];
}

// ------------------------------------------------------------------
// GEMM: h = tf32(x) @ tf32(W), h stored fp16.
// Block: 64 rows x 128 cols, K=128. 8 warps as 4(m) x 2(n); warp = 16x64.
__global__ __launch_bounds__(256) void k_gemm(
    const float* __restrict__ x, const float* __restrict__ W)
{
    extern __shared__ unsigned smem[];
    unsigned* usx = smem;                 // [64][SXS]
    unsigned* usw = smem + 64 * SXS;      // [128][SWS]

    const int tid  = threadIdx.x;
    const int warp = tid >> 5;
    const int lane = tid & 31;
    const int g    = lane >> 2;    // group id 0..7
    const int t4   = lane & 3;     // thread-in-group 0..3
    const int wm   = warp & 3;     // row warp 0..3
    const int wn   = warp >> 2;    // col warp 0..1
    const int row0 = blockIdx.x * 64;

    // stage x tile (convert to tf32)
    for (int idx = tid; idx < 64 * 32; idx += 256) {
        int r = idx >> 5, c4 = idx & 31;
        float4 v = {0.f, 0.f, 0.f, 0.f};
        if (row0 + r < NN) v = ((const float4*)x)[(size_t)(row0 + r) * 32 + c4];
        unsigned* d = &usx[r * SXS + c4 * 4];
        d[0] = f2tf32(v.x); d[1] = f2tf32(v.y); d[2] = f2tf32(v.z); d[3] = f2tf32(v.w);
    }
    // stage W (convert to tf32)
    for (int idx = tid; idx < 128 * 32; idx += 256) {
        int r = idx >> 5, c4 = idx & 31;
        float4 v = ((const float4*)W)[r * 32 + c4];
        unsigned* d = &usw[r * SWS + c4 * 4];
        d[0] = f2tf32(v.x); d[1] = f2tf32(v.y); d[2] = f2tf32(v.z); d[3] = f2tf32(v.w);
    }
    __syncthreads();

    float acc[8][4];
    #pragma unroll
    for (int t = 0; t < 8; t++) { acc[t][0]=0; acc[t][1]=0; acc[t][2]=0; acc[t][3]=0; }

    const int ar0 = (wm * 16 + g) * SXS;
    const int ar1 = (wm * 16 + g + 8) * SXS;
    const int nb  = wn * 64 + g;

    #pragma unroll
    for (int kt = 0; kt < 16; kt++) {
        const int k0 = kt * 8;
        unsigned a0 = usx[ar0 + k0 + t4];
        unsigned a1 = usx[ar1 + k0 + t4];
        unsigned a2 = usx[ar0 + k0 + t4 + 4];
        unsigned a3 = usx[ar1 + k0 + t4 + 4];
        const unsigned* w0 = &usw[(k0 + t4) * SWS + nb];
        const unsigned* w1 = &usw[(k0 + t4 + 4) * SWS + nb];
        #pragma unroll
        for (int t = 0; t < 8; t++) {
            unsigned b0 = w0[t * 8];
            unsigned b1 = w1[t * 8];
            mma_tf32(acc[t], a0, a1, a2, a3, b0, b1);
        }
    }

    // epilogue: fp16 store. c0/c1 at (row=g, col=2*t4(+1)), c2/c3 at row g+8.
    __half2* h2 = (__half2*)g_h16;
    const int r0 = row0 + wm * 16 + g;
    const int r1 = r0 + 8;
    #pragma unroll
    for (int t = 0; t < 8; t++) {
        int ch2 = wn * 32 + t * 4 + t4;    // half2 column index
        if (r0 < NN) h2[(size_t)r0 * 64 + ch2] = __floats2half2_rn(acc[t][0], acc[t][1]);
        if (r1 < NN) h2[(size_t)r1 * 64 + ch2] = __floats2half2_rn(acc[t][2], acc[t][3]);
    }
}

// ------------------------------------------------------------------
// attention dots: a_src/a_dst from fp16 h. One warp per node.
__global__ __launch_bounds__(256) void k_att(
    const float* __restrict__ attS, const float* __restrict__ attD)
{
    const int warp = threadIdx.x >> 5;
    const int lane = threadIdx.x & 31;
    const int node = blockIdx.x * 8 + warp;
    if (node >= NN) return;

    int2 hr = __ldg((const int2*)g_h16 + (size_t)node * 32 + lane);
    __half2 p0 = *reinterpret_cast<__half2*>(&hr.x);
    __half2 p1 = *reinterpret_cast<__half2*>(&hr.y);
    float2 f0 = __half22float2(p0);
    float2 f1 = __half22float2(p1);

    float4 vS = __ldg(&((const float4*)attS)[lane]);
    float4 vD = __ldg(&((const float4*)attD)[lane]);
    float s1 = f0.x * vS.x + f0.y * vS.y + f1.x * vS.z + f1.y * vS.w;
    float s2 = f0.x * vD.x + f0.y * vD.y + f1.x * vD.z + f1.y * vD.w;
    #pragma unroll
    for (int o = 4; o >= 1; o >>= 1) {
        s1 += __shfl_down_sync(0xFFFFFFFFu, s1, o);
        s2 += __shfl_down_sync(0xFFFFFFFFu, s2, o);
    }
    if ((lane & 7) == 0) {
        int hd = lane >> 3;
        g_as[node * HH + hd] = s1;
        g_ad[node * HH + hd] = s2;
    }
}

// ------------------------------------------------------------------
__global__ void k_hist(const void* __restrict__ ei) {
    int e = blockIdx.x * blockDim.x + threadIdx.x;
    if (e < EE) {
        int d = load_idx(ei, (long long)EE + e);
        atomicAdd(&g_cnt[d], 1);
    }
}

__global__ void k_scan1() {
    __shared__ int s[1024];
    int tid = threadIdx.x;
    int i = blockIdx.x * 1024 + tid;
    int v = (i < NN) ? g_cnt[i] : 0;
    s[tid] = v;
    __syncthreads();
    for (int o = 1; o < 1024; o <<= 1) {
        int t = (tid >= o) ? s[tid - o] : 0;
        __syncthreads();
        s[tid] += t;
        __syncthreads();
    }
    if (i < NN) g_off[i] = s[tid] - v;
    if (tid == 1023) g_bsums[blockIdx.x] = s[1023];
}

__global__ void k_scan2() {
    __shared__ int s[128];
    int tid = threadIdx.x;
    int v = (tid < SCAN_NB) ? g_bsums[tid] : 0;
    s[tid] = v;
    __syncthreads();
    for (int o = 1; o < 128; o <<= 1) {
        int t = (tid >= o) ? s[tid - o] : 0;
        __syncthreads();
        s[tid] += t;
        __syncthreads();
    }
    g_bsums[tid] = s[tid] - v;
}

__global__ void k_scan3() {
    int i = blockIdx.x * 1024 + threadIdx.x;
    if (i < NN) {
        int o = g_off[i] + g_bsums[blockIdx.x];
        g_off[i] = o;
        g_cur[i] = o;
    }
    if (i == 0) g_off[NN] = EE;
}

__global__ void k_scatter(const void* __restrict__ ei) {
    int e = blockIdx.x * blockDim.x + threadIdx.x;
    if (e < EE) {
        int s = load_idx(ei, e);
        int d = load_idx(ei, (long long)EE + e);
        int pos = atomicAdd(&g_cur[d], 1);
        g_csr[pos] = s;
    }
}

// ------------------------------------------------------------------
// Aggregation: warp per dst node; fp16 h gathers (8B/lane/edge), 2-deep pipeline.
__global__ __launch_bounds__(256) void k_agg(
    const float* __restrict__ bias, float* __restrict__ out)
{
    const int warp = threadIdx.x >> 5;
    const int lane = threadIdx.x & 31;
    const int i = blockIdx.x * 8 + warp;
    if (i >= NN) return;

    const int hd = lane >> 3;
    const float adv = g_ad[i * HH + hd];
    const int beg = g_off[i];
    const int end = g_off[i + 1];
    const int2* __restrict__ hp = (const int2*)g_h16;

    float ax = 0.f, ay = 0.f, az = 0.f, aw = 0.f, ps = 0.f;

    int e = beg;
    int  sn = 0; float asn = 0.f; int2 hrn = {0, 0};
    if (e < end) {
        sn  = __ldg(&g_csr[e]);
        asn = __ldg(&g_as[sn * HH + hd]);
        hrn = __ldg(hp + (size_t)sn * 32 + lane);
    }
    while (e < end) {
        float asv = asn; int2 hr = hrn;
        int en = e + 1;
        if (en < end) {
            sn  = __ldg(&g_csr[en]);
            asn = __ldg(&g_as[sn * HH + hd]);
            hrn = __ldg(hp + (size_t)sn * 32 + lane);
        }
        float ev = asv + adv;
        ev = ev > 0.f ? ev : SLOPE * ev;
        float p = __expf(ev);
        float2 f0 = __half22float2(*reinterpret_cast<__half2*>(&hr.x));
        float2 f1 = __half22float2(*reinterpret_cast<__half2*>(&hr.y));
        ax += p * f0.x; ay += p * f0.y; az += p * f1.x; aw += p * f1.y;
        ps += p;
        e = en;
    }
    // self-loop
    {
        float ev = __ldg(&g_as[i * HH + hd]) + adv;
        ev = ev > 0.f ? ev : SLOPE * ev;
        float p = __expf(ev);
        int2 hr = __ldg(hp + (size_t)i * 32 + lane);
        float2 f0 = __half22float2(*reinterpret_cast<__half2*>(&hr.x));
        float2 f1 = __half22float2(*reinterpret_cast<__half2*>(&hr.y));
        ax += p * f0.x; ay += p * f0.y; az += p * f1.x; aw += p * f1.y;
        ps += p;
    }

    const float inv = 1.0f / (ps + 1e-16f);
    float4 b = __ldg(&((const float4*)bias)[lane]);
    float4 o;
    o.x = ax * inv + b.x;
    o.y = ay * inv + b.y;
    o.z = az * inv + b.z;
    o.w = aw * inv + b.w;
    ((float4*)out)[(size_t)i * 32 + lane] = o;
}

// ------------------------------------------------------------------
extern "C" void kernel_launch(void* const* d_in, const int* in_sizes, int n_in,
                              void* d_out, int out_size)
{
    const float* x    = (const float*)d_in[0];
    const float* W    = (const float*)d_in[1];
    const float* attS = (const float*)d_in[2];
    const float* attD = (const float*)d_in[3];
    const float* bias = (const float*)d_in[4];
    const void*  ei   = d_in[5];
    float* out = (float*)d_out;

    cudaFuncSetAttribute(k_gemm, cudaFuncAttributeMaxDynamicSharedMemorySize, SMEM_BYTES);

    k_init<<<(NN + 255) / 256, 256>>>(ei);
    k_gemm<<<(NN + 63) / 64, 256, SMEM_BYTES>>>(x, W);
    k_att<<<(NN + 7) / 8, 256>>>(attS, attD);
    k_hist<<<(EE + 255) / 256, 256>>>(ei);
    k_scan1<<<SCAN_NB, 1024>>>();
    k_scan2<<<1, 128>>>();
    k_scan3<<<SCAN_NB, 1024>>>();
    k_scatter<<<(EE + 255) / 256, 256>>>(ei);
    k_agg<<<(NN + 7) / 8, 256>>>(bias, out);
}